// round 4
// baseline (speedup 1.0000x reference)
#include <cuda_runtime.h>
#include <cstdint>

// ---------------------------------------------------------------------------
// HebbianConv2d (sm_103 baseline ISA):
//   valid 3x3 conv (16,256,56,56)->(16,384,54,54) as implicit GEMM on the
//   FFMA f32x2 pipe. x is pre-copied into 3 kw-shifted buffers so every
//   B-operand load is an aligned LDG.128; A is staged duplicated (float2{a,a})
//   so the f32x2 broadcast needs no register packing. 128x128 tile, K-stage
//   32, 256 threads, 2 CTAs/SM. Then per-pixel WTA + Gaussian LFB gating.
// ---------------------------------------------------------------------------

#define B_SZ   16
#define CIN_   256
#define COUT_  384
#define HIN_   56
#define HO_    54
#define KDIM   2304                  // 256*9
#define IMG_N  3072                  // padded local-n per image (54*56 -> 3072)
#define NPAD   (B_SZ * IMG_N)        // 49152
#define IMG_SZ (CIN_ * HIN_ * HIN_)  // 802816 floats per image
#define XELEMS ((size_t)B_SZ * IMG_SZ)   // 12,845,056
#define XP     (XELEMS + 4096)       // per-copy slack for tile-tail reads

typedef unsigned long long ull;

__device__ float g_xs[3 * XP];                  // kw-shifted copies of x (~154 MB)
__device__ float g_y[(size_t)NPAD * COUT_];     // pixel-major [padded n][cout]
__device__ float g_pad;

__device__ __forceinline__ void ffma2(ull &c, ull a, ull b) {
    asm("fma.rn.f32x2 %0, %1, %2, %0;" : "+l"(c) : "l"(a), "l"(b));
}

// ---------------------------------------------------------------------------
// copy x into 3 shifted padded buffers: g_xs[kw][i] = x[i + kw]
// ---------------------------------------------------------------------------
__global__ void copy_x3_kernel(const float* __restrict__ x) {
    size_t i = (size_t)blockIdx.x * 256 + threadIdx.x;
    size_t n4 = XELEMS / 4;
    if (i < n4) {
        float4 a = ((const float4*)x)[i];
        float4 b = (i + 1 < n4) ? ((const float4*)x)[i + 1] : a;
        ((float4*)g_xs)[i]            = a;
        ((float4*)(g_xs + XP))[i]     = make_float4(a.y, a.z, a.w, b.x);
        ((float4*)(g_xs + 2 * XP))[i] = make_float4(a.z, a.w, b.x, b.y);
    }
}

__global__ void pad_kernel() { if (threadIdx.x == 0) g_pad = 1.0f; }

// ---------------------------------------------------------------------------
// Conv GEMM: y[m][n] = sum_k W[m][k] * Xs[kw(k)][img(n) + off(k) + nl(n)]
//   CTA tile: M=128 x N=128, K-stage=32, double buffered, 256 threads,
//   2 CTAs/SM. Dynamic smem: As2 (dup float2) 64KB + Bs 32KB = 96KB.
// ---------------------------------------------------------------------------
#define KS 32
#define SMEM_CONV (2*KS*128*8 + 2*KS*128*4)     // 98304

__global__ __launch_bounds__(256, 2)
void conv_gemm_kernel(const float* __restrict__ Wg)
{
    extern __shared__ char smem[];
    float2* As2 = (float2*)smem;                  // [(buf*KS + k)*128 + m]
    float*  Bs  = (float*)(smem + 2*KS*128*8);    // [(buf*KS + k)*128 + n]

    const int tid  = threadIdx.x;
    const int lane = tid & 31;
    const int wid  = tid >> 5;            // 0..7
    const int tx   = tid & 15;            // n group (dedup x2 per warp)
    const int ty   = tid >> 4;            // m group

    const int m0   = blockIdx.x * 128;              // m fastest: L2 reuse of B
    const int bimg = blockIdx.y / 24;
    const int nl0  = (blockIdx.y - bimg * 24) * 128;
    const int imgb = bimg * IMG_SZ;

    // A-load role: 4 float4 per stage (rows of W)
    const int arow = tid >> 1;            // 0..127
    const int akq  = (tid & 1) * 16;      // k offset 0 or 16
    const float* Abase = Wg + (size_t)(m0 + arow) * KDIM + akq;

    ull acc[8][4];
#pragma unroll
    for (int i = 0; i < 8; i++)
#pragma unroll
        for (int j = 0; j < 4; j++) acc[i][j] = 0ull;

    float4 avs[4], bvs[4];

    auto load_stage = [&](int s) {
        const int k0 = s * KS;
#pragma unroll
        for (int j = 0; j < 4; j++)
            avs[j] = *(const float4*)(Abase + k0 + j * 4);
#pragma unroll
        for (int j = 0; j < 4; j++) {
            int k  = k0 + wid * 4 + j;
            int ci = k / 9;
            int r  = k - ci * 9;
            int kh = r / 3;
            int kw = r - kh * 3;
            const float* src = g_xs + (size_t)kw * XP + imgb
                             + ci * (HIN_ * HIN_) + kh * HIN_ + nl0 + lane * 4;
            bvs[j] = *(const float4*)src;
        }
    };

    auto store_stage = [&](int buf) {
        float2* Ad = As2 + (size_t)buf * KS * 128;
#pragma unroll
        for (int j = 0; j < 4; j++) {
            float v0 = avs[j].x, v1 = avs[j].y, v2 = avs[j].z, v3 = avs[j].w;
            int kb = akq + j * 4;
            Ad[(kb + 0) * 128 + arow] = make_float2(v0, v0);
            Ad[(kb + 1) * 128 + arow] = make_float2(v1, v1);
            Ad[(kb + 2) * 128 + arow] = make_float2(v2, v2);
            Ad[(kb + 3) * 128 + arow] = make_float2(v3, v3);
        }
        float* Bd = Bs + (size_t)buf * KS * 128;
#pragma unroll
        for (int j = 0; j < 4; j++)
            *(float4*)&Bd[(wid * 4 + j) * 128 + lane * 4] = bvs[j];
    };

    auto compute_stage = [&](int buf) {
        const float2* Ab = As2 + (size_t)buf * KS * 128 + ty * 8;
        const float*  Bb = Bs  + (size_t)buf * KS * 128 + tx * 8;
#pragma unroll 16
        for (int kk = 0; kk < KS; kk++) {
            const ulonglong2* ap = (const ulonglong2*)(Ab + (size_t)kk * 128);
            ulonglong2 a01 = ap[0], a23 = ap[1], a45 = ap[2], a67 = ap[3];
            ull a[8] = { a01.x, a01.y, a23.x, a23.y, a45.x, a45.y, a67.x, a67.y };

            const ulonglong2* bp = (const ulonglong2*)(Bb + (size_t)kk * 128);
            ulonglong2 b01 = bp[0], b23 = bp[1];
            ull bb[4] = { b01.x, b01.y, b23.x, b23.y };

#pragma unroll
            for (int mi = 0; mi < 8; mi++)
#pragma unroll
                for (int nj = 0; nj < 4; nj++)
                    ffma2(acc[mi][nj], a[mi], bb[nj]);
        }
    };

    load_stage(0);
    store_stage(0);
    __syncthreads();
    for (int s = 0; s < KDIM / KS - 1; s++) {
        load_stage(s + 1);
        compute_stage(s & 1);
        store_stage((s + 1) & 1);
        __syncthreads();
    }
    compute_stage((KDIM / KS - 1) & 1);

    // ---- store: g_y[padded n][m], m-contiguous per pixel ----
    const int n0g = bimg * IMG_N + nl0;
    union { ull u; float f[2]; } cv;
#pragma unroll
    for (int nj = 0; nj < 4; nj++) {
#pragma unroll
        for (int half = 0; half < 2; half++) {
            int n = n0g + tx * 8 + nj * 2 + half;
            float v[8];
#pragma unroll
            for (int mi = 0; mi < 8; mi++) { cv.u = acc[mi][nj]; v[mi] = cv.f[half]; }
            float* dst = g_y + (size_t)n * COUT_ + m0 + ty * 8;
            *(float4*)(dst + 0) = make_float4(v[0], v[1], v[2], v[3]);
            *(float4*)(dst + 4) = make_float4(v[4], v[5], v[6], v[7]);
        }
    }
}

// ---------------------------------------------------------------------------
// WTA + Gaussian lateral feedback gating (27 pixels per block)
// ---------------------------------------------------------------------------
#define SYP 388

__global__ __launch_bounds__(256) void wta_lfb_kernel(float* __restrict__ out) {
    __shared__ float sy[27 * SYP];
    __shared__ int   wcnt[27];
    __shared__ int   wlist[27][4];

    const int tid = threadIdx.x;
    const int b   = blockIdx.z;
    const int h   = blockIdx.y;
    const int w0  = blockIdx.x * 27;

    const size_t base = ((size_t)b * IMG_N + h * HIN_ + w0) * COUT_;

    for (int i4 = tid; i4 < 27 * 96; i4 += 256) {
        float4 v = *(const float4*)(g_y + base + (size_t)i4 * 4);
        int j  = i4 / 96;
        int c4 = i4 - j * 96;
        *(float4*)&sy[j * SYP + c4 * 4] = v;
    }
    if (tid < 27) wcnt[tid] = 0;
    __syncthreads();

    const int wid  = tid >> 5;
    const int lane = tid & 31;
    for (int j = wid; j < 27; j += 8) {
        const float* p = &sy[j * SYP];
        float mx = -3.4e38f;
#pragma unroll
        for (int q = 0; q < 12; q++) mx = fmaxf(mx, p[lane + q * 32]);
#pragma unroll
        for (int o = 16; o; o >>= 1) mx = fmaxf(mx, __shfl_xor_sync(0xffffffffu, mx, o));
#pragma unroll
        for (int q = 0; q < 12; q++) {
            int c = lane + q * 32;
            if (p[c] == mx) {
                int pos = atomicAdd(&wcnt[j], 1);
                if (pos < 4) wlist[j][pos] = c;
            }
        }
    }
    __syncthreads();

    const float inv2s2 = 1.0f / (2.0f * 191.0f * 191.0f);
    for (int i = tid; i < COUT_ * 27; i += 256) {
        int c = i / 27;
        int j = i - c * 27;
        float yv = sy[j * SYP + c];
        int nw = wcnt[j]; if (nw > 4) nw = 4;
        float lfb = 0.0f;
        for (int t = 0; t < nw; t++) {
            int d = wlist[j][t] - c;
            if (d >= -191 && d <= 192)
                lfb += __expf(-(float)(d * d) * inv2s2);
        }
        lfb = fminf(lfb, 1.0f);
        out[(((size_t)b * COUT_ + c) * HO_ + h) * HO_ + w0 + j] = lfb * yv;
    }
}

// ---------------------------------------------------------------------------
extern "C" void kernel_launch(void* const* d_in, const int* in_sizes, int n_in,
                              void* d_out, int out_size) {
    const float* x = (const float*)d_in[0];   // (16,256,56,56)
    const float* w = (const float*)d_in[1];   // (384,256,3,3)
    float* out = (float*)d_out;               // (16,384,54,54)

    cudaFuncSetAttribute(conv_gemm_kernel,
                         cudaFuncAttributeMaxDynamicSharedMemorySize, SMEM_CONV);

    copy_x3_kernel<<<(unsigned)((XELEMS / 4 + 255) / 256), 256>>>(x);
    pad_kernel<<<1, 32>>>();                  // profiler alignment: conv at
    pad_kernel<<<1, 32>>>();                  //   replay idx 3 (= ncu -s 5 target)

    dim3 g1(3, B_SZ * 24);                    // m fastest -> B reuse in L2
    conv_gemm_kernel<<<g1, 256, SMEM_CONV>>>(w);

    dim3 g2(2, HO_, B_SZ);
    wta_lfb_kernel<<<g2, 256>>>(out);
}

// round 5
// speedup vs baseline: 1.6215x; 1.6215x over previous
#include <cuda_runtime.h>
#include <cstdint>

// ---------------------------------------------------------------------------
// HebbianConv2d (sm_103 baseline ISA):
//   valid 3x3 conv (16,256,56,56)->(16,384,54,54) as implicit GEMM on the
//   FFMA f32x2 pipe. cp.async feeds SMEM directly (zero staging registers ->
//   no spills, which killed R4). W pre-transposed to [k][m] so the A operand
//   is read as m-contiguous f32x2 pairs. 3-slot cp.async pipeline, 128x128
//   tile, KS=32, 256 threads, 2 CTAs/SM. Then WTA + Gaussian LFB gating.
// ---------------------------------------------------------------------------

#define B_SZ   16
#define CIN_   256
#define COUT_  384
#define HIN_   56
#define HO_    54
#define KDIM   2304                  // 256*9
#define IMG_N  3072                  // padded local-n per image
#define NPAD   (B_SZ * IMG_N)        // 49152
#define IMG_SZ (CIN_ * HIN_ * HIN_)  // 802816
#define XELEMS ((size_t)B_SZ * IMG_SZ)
#define XP     (XELEMS + 4096)

typedef unsigned long long ull;

__device__ float g_xs[3 * XP];                  // kw-shifted copies of x
__device__ float g_wt[KDIM * COUT_];            // W transposed: [k][m]
__device__ float g_y[(size_t)NPAD * COUT_];     // pixel-major [padded n][m]
__device__ float g_pad;

__device__ __forceinline__ void ffma2(ull &c, ull a, ull b) {
    asm("fma.rn.f32x2 %0, %1, %2, %0;" : "+l"(c) : "l"(a), "l"(b));
}
__device__ __forceinline__ ull dup2(float a) {
    ull r;
    asm("mov.b64 %0, {%1, %1};" : "=l"(r) : "f"(a));
    return r;
}
__device__ __forceinline__ uint32_t smem_u32(const void* p) {
    uint32_t a;
    asm("{ .reg .u64 t; cvta.to.shared.u64 t, %1; cvt.u32.u64 %0, t; }"
        : "=r"(a) : "l"(p));
    return a;
}
__device__ __forceinline__ void cp16(uint32_t dst, const float* src) {
    asm volatile("cp.async.cg.shared.global [%0], [%1], 16;"
                 :: "r"(dst), "l"(src) : "memory");
}
#define CP_COMMIT() asm volatile("cp.async.commit_group;" ::: "memory")
#define CP_WAIT1()  asm volatile("cp.async.wait_group 1;" ::: "memory")

// ---------------------------------------------------------------------------
__global__ void copy_x3_kernel(const float* __restrict__ x) {
    size_t i = (size_t)blockIdx.x * 256 + threadIdx.x;
    size_t n4 = XELEMS / 4;
    if (i < n4) {
        float4 a = ((const float4*)x)[i];
        float4 b = (i + 1 < n4) ? ((const float4*)x)[i + 1] : a;
        ((float4*)g_xs)[i]            = a;
        ((float4*)(g_xs + XP))[i]     = make_float4(a.y, a.z, a.w, b.x);
        ((float4*)(g_xs + 2 * XP))[i] = make_float4(a.z, a.w, b.x, b.y);
    }
}

__global__ void transpose_w_kernel(const float* __restrict__ w) {
    // g_wt[k][m] = w[m][k]; thread = k fastest for coalesced reads
    int i = blockIdx.x * 256 + threadIdx.x;     // i = m*KDIM + k
    if (i < COUT_ * KDIM) {
        int m = i / KDIM;
        int k = i - m * KDIM;
        g_wt[k * COUT_ + m] = w[i];
    }
}

__global__ void pad_kernel() { if (threadIdx.x == 0) g_pad = 1.0f; }

// ---------------------------------------------------------------------------
// Conv GEMM: tile M=128 x N=128, KS=32, 256 threads, 2 CTAs/SM.
// SMEM: 3 slots x (A 16KB + B 16KB) = 96KB. cp.async pipeline depth 3.
// ---------------------------------------------------------------------------
#define KS        32
#define SLOT_B    (2 * KS * 128 * 4)            // 32KB per slot
#define SMEM_CONV (3 * SLOT_B)                  // 96KB
#define NSTAGE    (KDIM / KS)                   // 72

__global__ __launch_bounds__(256, 2)
void conv_gemm_kernel()
{
    extern __shared__ char smem[];
    const uint32_t sb = smem_u32(smem);

    const int tid  = threadIdx.x;
    const int lane = tid & 31;
    const int wid  = tid >> 5;                  // 0..7

    // warp grid: 2 m-warps x 4 n-warps; lane grid: 8 m-groups x 4 n-groups
    const int tm = (lane >> 2) * 8 + (wid & 1) * 64;   // 8 m per thread
    const int tn = (lane & 3) * 8 + (wid >> 1) * 32;   // 8 n per thread

    const int m0   = blockIdx.x * 128;
    const int bimg = blockIdx.y / 24;
    const int nl0  = (blockIdx.y - bimg * 24) * 128;
    const int imgb = bimg * IMG_SZ;

    // cp.async roles: row = j*8 + wid (k within stage), col = lane (16B chunk)
    const float* Abase = g_wt + m0 + lane * 4;          // + k*384
    const int    bcol  = nl0 + lane * 4;

    ull acc[4][8];
#pragma unroll
    for (int i = 0; i < 4; i++)
#pragma unroll
        for (int j = 0; j < 8; j++) acc[i][j] = 0ull;

    auto issue_stage = [&](int s, int slot) {
        const int k0 = s * KS;
        const uint32_t sa = sb + slot * SLOT_B;
#pragma unroll
        for (int j = 0; j < 4; j++) {
            int row = j * 8 + wid;
            cp16(sa + row * 512 + lane * 16, Abase + (size_t)(k0 + row) * COUT_);
        }
#pragma unroll
        for (int j = 0; j < 4; j++) {
            int row = j * 8 + wid;
            int k  = k0 + row;
            int ci = k / 9;
            int r  = k - ci * 9;
            int kh = r / 3;
            int kw = r - kh * 3;
            const float* src = g_xs + (size_t)kw * XP + imgb
                             + ci * (HIN_ * HIN_) + kh * HIN_ + bcol;
            cp16(sa + 16384 + row * 512 + lane * 16, src);
        }
        CP_COMMIT();
    };

    auto compute_stage = [&](int slot) {
        const char* base = smem + slot * SLOT_B;
        const float* Ab = (const float*)base + tm;
        const float* Bb = (const float*)(base + 16384) + tn;
#pragma unroll
        for (int kk = 0; kk < KS; kk++) {
            ulonglong2 a01 = *(const ulonglong2*)(Ab + kk * 128);
            ulonglong2 a23 = *(const ulonglong2*)(Ab + kk * 128 + 4);
            ull a[4] = { a01.x, a01.y, a23.x, a23.y };

            float4 b0 = *(const float4*)(Bb + kk * 128);
            float4 b1 = *(const float4*)(Bb + kk * 128 + 4);
            ull bd[8] = { dup2(b0.x), dup2(b0.y), dup2(b0.z), dup2(b0.w),
                          dup2(b1.x), dup2(b1.y), dup2(b1.z), dup2(b1.w) };

#pragma unroll
            for (int mi = 0; mi < 4; mi++)
#pragma unroll
                for (int nj = 0; nj < 8; nj++)
                    ffma2(acc[mi][nj], a[mi], bd[nj]);
        }
    };

    // pipeline: depth 3, one barrier per stage
    issue_stage(0, 0);
    issue_stage(1, 1);
    for (int s = 0; s < NSTAGE; s++) {
        CP_WAIT1();                 // stage s landed
        __syncthreads();            // all threads done with compute(s-1)
        if (s + 2 < NSTAGE) issue_stage(s + 2, (s + 2) % 3);
        else CP_COMMIT();           // keep group accounting consistent
        compute_stage(s % 3);
    }

    // ---- store: g_y[padded n][m] (8 consecutive m per thread) ----
    const int n0g = bimg * IMG_N + nl0;
    union { ull u; float f[2]; } c0, c1;
#pragma unroll
    for (int nj = 0; nj < 8; nj++) {
        int n = n0g + tn + nj;
        float* dst = g_y + (size_t)n * COUT_ + m0 + tm;
        c0.u = acc[0][nj]; c1.u = acc[1][nj];
        *(float4*)(dst + 0) = make_float4(c0.f[0], c0.f[1], c1.f[0], c1.f[1]);
        c0.u = acc[2][nj]; c1.u = acc[3][nj];
        *(float4*)(dst + 4) = make_float4(c0.f[0], c0.f[1], c1.f[0], c1.f[1]);
    }
}

// ---------------------------------------------------------------------------
// WTA + Gaussian lateral feedback gating (27 pixels per block)
// ---------------------------------------------------------------------------
#define SYP 388

__global__ __launch_bounds__(256) void wta_lfb_kernel(float* __restrict__ out) {
    __shared__ float sy[27 * SYP];
    __shared__ int   wcnt[27];
    __shared__ int   wlist[27][4];

    const int tid = threadIdx.x;
    const int b   = blockIdx.z;
    const int h   = blockIdx.y;
    const int w0  = blockIdx.x * 27;

    const size_t base = ((size_t)b * IMG_N + h * HIN_ + w0) * COUT_;

    for (int i4 = tid; i4 < 27 * 96; i4 += 256) {
        float4 v = *(const float4*)(g_y + base + (size_t)i4 * 4);
        int j  = i4 / 96;
        int c4 = i4 - j * 96;
        *(float4*)&sy[j * SYP + c4 * 4] = v;
    }
    if (tid < 27) wcnt[tid] = 0;
    __syncthreads();

    const int wid  = tid >> 5;
    const int lane = tid & 31;
    for (int j = wid; j < 27; j += 8) {
        const float* p = &sy[j * SYP];
        float mx = -3.4e38f;
#pragma unroll
        for (int q = 0; q < 12; q++) mx = fmaxf(mx, p[lane + q * 32]);
#pragma unroll
        for (int o = 16; o; o >>= 1) mx = fmaxf(mx, __shfl_xor_sync(0xffffffffu, mx, o));
#pragma unroll
        for (int q = 0; q < 12; q++) {
            int c = lane + q * 32;
            if (p[c] == mx) {
                int pos = atomicAdd(&wcnt[j], 1);
                if (pos < 4) wlist[j][pos] = c;
            }
        }
    }
    __syncthreads();

    const float inv2s2 = 1.0f / (2.0f * 191.0f * 191.0f);
    for (int i = tid; i < COUT_ * 27; i += 256) {
        int c = i / 27;
        int j = i - c * 27;
        float yv = sy[j * SYP + c];
        int nw = wcnt[j]; if (nw > 4) nw = 4;
        float lfb = 0.0f;
        for (int t = 0; t < nw; t++) {
            int d = wlist[j][t] - c;
            if (d >= -191 && d <= 192)
                lfb += __expf(-(float)(d * d) * inv2s2);
        }
        lfb = fminf(lfb, 1.0f);
        out[(((size_t)b * COUT_ + c) * HO_ + h) * HO_ + w0 + j] = lfb * yv;
    }
}

// ---------------------------------------------------------------------------
extern "C" void kernel_launch(void* const* d_in, const int* in_sizes, int n_in,
                              void* d_out, int out_size) {
    const float* x = (const float*)d_in[0];   // (16,256,56,56)
    const float* w = (const float*)d_in[1];   // (384,256,3,3)
    float* out = (float*)d_out;               // (16,384,54,54)

    cudaFuncSetAttribute(conv_gemm_kernel,
                         cudaFuncAttributeMaxDynamicSharedMemorySize, SMEM_CONV);

    copy_x3_kernel<<<(unsigned)((XELEMS / 4 + 255) / 256), 256>>>(x);
    transpose_w_kernel<<<(COUT_ * KDIM + 255) / 256, 256>>>(w);
    pad_kernel<<<1, 32>>>();                  // conv stays at launch idx 3 (ncu -s 5)

    dim3 g1(3, B_SZ * 24);                    // m fastest -> B reuse in L2
    conv_gemm_kernel<<<g1, 256, SMEM_CONV>>>();

    dim3 g2(2, HO_, B_SZ);
    wta_lfb_kernel<<<g2, 256>>>(out);
}